// round 17
// baseline (speedup 1.0000x reference)
#include <cuda_runtime.h>
#include <cuda_bf16.h>
#include <cuda_fp16.h>
#include <cstdint>
#include <cstddef>

// ---------------------------------------------------------------------------
// Show-Attend-Tell decoder. Round 15 = R14 + 2-pass bf16 enc_proj:
// the enc_proj GEMM drops the Ah*Bl correction pass (error enters only the
// softmax-protected scores path; measured transfer 0.1 -> +2e-4 final).
// All recurrent/output GEMMs stay exact-class 3-pass.
// ---------------------------------------------------------------------------

constexpr int B    = 128;
constexpr int P    = 196;
constexpr int ENC  = 2048;
constexpr int EMB  = 512;
constexpr int DEC  = 512;
constexpr int ATT  = 512;
constexpr int VOC  = 10000;
constexpr int T    = 20;
constexpr int NSTEP = T - 1;           // 19
constexpr int G4   = 4 * DEC;          // 2048
constexpr int HALLN = ATT + ENC + G4;  // 4608
constexpr int COMBN = HALLN + VOC;     // 14608
constexpr int XDIM = EMB + ENC;        // 2560
constexpr int KSPLIT = 8;
constexpr int KCHUNK = XDIM / KSPLIT;  // 320

using bf16 = __nv_bfloat16;

// ----------------------------- device scratch ------------------------------
__device__ float g_hc[B * 2 * DEC];
__device__ float g_c[B * DEC];
__device__ __align__(16) bf16  g_h_h[B * DEC];
__device__ __align__(16) bf16  g_h_l[B * DEC];
__device__ __align__(16) bf16  g_mean_h[B * ENC];
__device__ __align__(16) bf16  g_mean_l[B * ENC];
__device__ __align__(16) bf16  g_x_h[B * XDIM];
__device__ __align__(16) bf16  g_x_l[B * XDIM];
__device__ __align__(16) bf16  g_E_h[(size_t)B * P * ENC];
__device__ __align__(16) bf16  g_E_l[(size_t)B * P * ENC];
__device__ __align__(16) __half g_E16[(size_t)B * P * ENC];     // context-only
__device__ __align__(16) __half g_encproj[(size_t)B * P * ATT]; // fp16 (scores)
__device__ float g_hall[B * HALLN];
__device__ float g_alpha[B * P];
__device__ float g_gpart[(size_t)16 * B * G4];
// packed / transposed weights (bf16 hi/lo planes, [N][K] layout)
__device__ __align__(16) bf16 g_WencT_h[ATT * ENC];
__device__ __align__(16) bf16 g_WencT_l[ATT * ENC];
__device__ __align__(16) bf16 g_WinitT_h[2 * DEC * ENC];
__device__ __align__(16) bf16 g_WinitT_l[2 * DEC * ENC];
__device__ __align__(16) bf16 g_WcombT_h[COMBN * DEC];  // [Wall|Wfc]
__device__ __align__(16) bf16 g_WcombT_l[COMBN * DEC];
__device__ __align__(16) bf16 g_WihT_h[G4 * XDIM];
__device__ __align__(16) bf16 g_WihT_l[G4 * XDIM];
__device__ float g_ball[HALLN];
__device__ float g_binit[2 * DEC];

// ------------------------------ helpers -------------------------------------
__device__ __forceinline__ void splitbf(float x, bf16& h, bf16& l) {
    h = __float2bfloat16(x);
    l = __float2bfloat16(x - __bfloat162float(h));
}

__device__ __forceinline__ void mma_bf16(float c[4], const uint32_t a[4],
                                         const uint32_t b[2]) {
    asm volatile(
        "mma.sync.aligned.m16n8k16.row.col.f32.bf16.bf16.f32 "
        "{%0,%1,%2,%3}, {%4,%5,%6,%7}, {%8,%9}, {%0,%1,%2,%3};"
        : "+f"(c[0]), "+f"(c[1]), "+f"(c[2]), "+f"(c[3])
        : "r"(a[0]), "r"(a[1]), "r"(a[2]), "r"(a[3]), "r"(b[0]), "r"(b[1]));
}

__device__ __forceinline__ void ldsm4(uint32_t& r0, uint32_t& r1, uint32_t& r2,
                                      uint32_t& r3, uint32_t addr) {
    asm volatile(
        "ldmatrix.sync.aligned.m8n8.x4.shared.b16 {%0,%1,%2,%3}, [%4];"
        : "=r"(r0), "=r"(r1), "=r"(r2), "=r"(r3) : "r"(addr));
}

__device__ __forceinline__ void cpasync16(uint32_t dst, const void* src) {
    asm volatile("cp.async.cg.shared.global [%0], [%1], 16;"
                 :: "r"(dst), "l"(src));
}

// ------------------------------ split-BF16 GEMM ------------------------------
// C[M,N] = (Ah+Al)[M,K] @ (Bh+Bl)^T[N,K]. K-major bf16 operands.
// PASSES=3: Ah*Bh + Al*Bh + Ah*Bl (fp32-equivalent class).
// PASSES=2: Ah*Bh + Al*Bh (drops weight-lo; ~2^-9 rel err — softmax paths only).
// BM=128, BN=2*NT*8. 256 thr, 8 warps (4Mx2N), warp tile 32x(NT*8).
// cp.async STAGES-deep pipeline + ldmatrix.x4, PADK=20.
// OUT16: Cv is __half* (single destination; N1/C2/bias2 ignored).
// Otherwise dual destination: cols < N1 -> Cv fp32 (ldc, bias);
// cols >= N1 -> C2 fp32 (ldc2, bias2).
// Split-K: z selects [z*kChunk,...), C += z*M*ldc (fp32 single-dest use only).
// Requires M%128==0, kChunk%32==0, K%8==0, nIter>=2. N tail: rows clamped,
// cols guarded.
constexpr int PADK = 20;

extern __shared__ uint32_t dynsm[];

template <int NT, bool OUT16, int STAGES, int PASSES>
__global__ void __launch_bounds__(256, 2)
gemm_bf3(const bf16* __restrict__ Ah, const bf16* __restrict__ Al,
         const bf16* __restrict__ Bh, const bf16* __restrict__ Bl,
         void* __restrict__ Cv, float* __restrict__ C2,
         int M, int N, int N1, int K, int ldc, int ldc2,
         const float* __restrict__ bias, const float* __restrict__ bias2,
         int kChunk) {
    constexpr int BN     = 2 * NT * 8;
    constexpr int APLANE = 128 * PADK;
    constexpr int BPLANE = BN * PADK;
    constexpr int NBPL   = (PASSES == 3) ? 2 : 1;     // B planes staged
    constexpr int STAGE  = 2 * APLANE + NBPL * BPLANE;
    constexpr int BLOADS = BN / 64;

    const int tid  = threadIdx.x;
    const int warp = tid >> 5;
    const int lane = tid & 31;
    const int lr   = lane >> 2;
    const int lq   = lane & 3;
    const int wm   = warp & 3;
    const int wn   = warp >> 2;
    const int rowBase = blockIdx.y * 128;
    const int colBase = blockIdx.x * BN;
    const int k0 = blockIdx.z * kChunk;
    const int nIter = kChunk / 32;

    const uint32_t smemBase = (uint32_t)__cvta_generic_to_shared(dynsm);

    auto load_stage = [&](int it, int stg) {
        const int kb = k0 + it * 32;
        const uint32_t sb = smemBase + (uint32_t)(stg * STAGE) * 4;
#pragma unroll
        for (int i = 0; i < 2; i++) {
            int idx = tid + i * 256;
            int r = idx >> 2, ch = idx & 3;
            const size_t off = (size_t)(rowBase + r) * K + kb + ch * 8;
            const uint32_t d = (uint32_t)(r * PADK + ch * 4) * 4;
            cpasync16(sb + d,              Ah + off);
            cpasync16(sb + APLANE * 4 + d, Al + off);
        }
#pragma unroll
        for (int i = 0; i < BLOADS; i++) {
            int idx = tid + i * 256;
            int r = idx >> 2, ch = idx & 3;
            const int n = min(colBase + r, N - 1);
            const size_t off = (size_t)n * K + kb + ch * 8;
            const uint32_t d = (uint32_t)(r * PADK + ch * 4) * 4;
            cpasync16(sb + 2u * APLANE * 4 + d, Bh + off);
            if (PASSES == 3)
                cpasync16(sb + (2u * APLANE + BPLANE) * 4 + d, Bl + off);
        }
    };

    const int aRow = (lane & 7) + ((lane >> 3) & 1) * 8;
    const int aK   = ((lane >> 4) & 1) * 4;
    const int bRow = (lane & 7) + ((lane >> 4) & 1) * 8;
    const int bK   = ((lane >> 3) & 1) * 4;

    float acc[2][NT][4];
#pragma unroll
    for (int mt = 0; mt < 2; mt++)
#pragma unroll
        for (int nt = 0; nt < NT; nt++)
#pragma unroll
            for (int j = 0; j < 4; j++) acc[mt][nt][j] = 0.f;

    // prologue: fill STAGES-1 stages
    load_stage(0, 0);
    asm volatile("cp.async.commit_group;");
    if (STAGES == 3) {
        load_stage(1, 1);
        asm volatile("cp.async.commit_group;");
    }

    for (int it = 0; it < nIter; it++) {
        if (STAGES == 2) {
            if (it + 1 < nIter) {
                load_stage(it + 1, (it + 1) & 1);
                asm volatile("cp.async.commit_group;");
                asm volatile("cp.async.wait_group 1;");
            } else {
                asm volatile("cp.async.wait_group 0;");
            }
        } else {
            if (it + 2 < nIter) {
                load_stage(it + 2, (it + 2) % 3);
                asm volatile("cp.async.commit_group;");
                asm volatile("cp.async.wait_group 2;");
            } else if (it + 1 < nIter) {
                asm volatile("cp.async.wait_group 1;");
            } else {
                asm volatile("cp.async.wait_group 0;");
            }
        }
        __syncthreads();

        const int stg = (STAGES == 2) ? (it & 1) : (it % 3);
        const uint32_t sb = smemBase + (uint32_t)(stg * STAGE) * 4;
#pragma unroll
        for (int s = 0; s < 2; s++) {
            const uint32_t ks = (uint32_t)(s * 8) * 4;
            uint32_t ah[2][4], al[2][4], bh[NT][2], bl[NT][2];
#pragma unroll
            for (int mt = 0; mt < 2; mt++) {
                uint32_t ra = (uint32_t)((wm * 32 + mt * 16 + aRow) * PADK +
                                         aK) * 4 + ks;
                ldsm4(ah[mt][0], ah[mt][1], ah[mt][2], ah[mt][3], sb + ra);
                ldsm4(al[mt][0], al[mt][1], al[mt][2], al[mt][3],
                      sb + APLANE * 4 + ra);
            }
#pragma unroll
            for (int np = 0; np < NT / 2; np++) {
                uint32_t rb = (uint32_t)((wn * NT * 8 + np * 16 + bRow) *
                                         PADK + bK) * 4 + ks;
                ldsm4(bh[2 * np][0], bh[2 * np][1], bh[2 * np + 1][0],
                      bh[2 * np + 1][1], sb + 2u * APLANE * 4 + rb);
                if (PASSES == 3)
                    ldsm4(bl[2 * np][0], bl[2 * np][1], bl[2 * np + 1][0],
                          bl[2 * np + 1][1],
                          sb + (2u * APLANE + BPLANE) * 4 + rb);
            }
#pragma unroll
            for (int nt = 0; nt < NT; nt++)
#pragma unroll
                for (int mt = 0; mt < 2; mt++) {
                    mma_bf16(acc[mt][nt], ah[mt], bh[nt]);
                    mma_bf16(acc[mt][nt], al[mt], bh[nt]);
                    if (PASSES == 3) mma_bf16(acc[mt][nt], ah[mt], bl[nt]);
                }
        }
        __syncthreads();
    }

#pragma unroll
    for (int mt = 0; mt < 2; mt++) {
        int r0 = rowBase + wm * 32 + mt * 16 + lr;
#pragma unroll
        for (int nt = 0; nt < NT; nt++) {
            int cbase = colBase + wn * NT * 8 + nt * 8 + 2 * lq;
#pragma unroll
            for (int cc = 0; cc < 2; cc++) {
                int c = cbase + cc;
                if (c >= N) continue;
                float v0 = acc[mt][nt][cc];
                float v1 = acc[mt][nt][2 + cc];
                if (OUT16) {
                    __half* C16 = (__half*)Cv;
                    float bb = bias ? bias[c] : 0.f;
                    C16[(size_t)r0 * ldc + c] = __float2half_rn(v0 + bb);
                    C16[(size_t)(r0 + 8) * ldc + c] = __float2half_rn(v1 + bb);
                } else {
                    float* C = (float*)Cv + (size_t)blockIdx.z * M * ldc;
                    if (c < N1) {
                        float bb = bias ? bias[c] : 0.f;
                        C[(size_t)r0 * ldc + c] = v0 + bb;
                        C[(size_t)(r0 + 8) * ldc + c] = v1 + bb;
                    } else {
                        int c2 = c - N1;
                        float bb = bias2 ? bias2[c2] : 0.f;
                        C2[(size_t)r0 * ldc2 + c2] = v0 + bb;
                        C2[(size_t)(r0 + 8) * ldc2 + c2] = v1 + bb;
                    }
                }
            }
        }
    }
}

constexpr int SMEM_N8_2_P3 = 2 * (2 * 128 * PADK + 2 * 128 * PADK) * 4;  // 81920
constexpr int SMEM_N8_2_P2 = 2 * (2 * 128 * PADK + 1 * 128 * PADK) * 4;  // 61440
constexpr int SMEM_N4_3_P3 = 3 * (2 * 128 * PADK + 2 * 64  * PADK) * 4;  // 92160

// ---------------------- coalesced transpose + split --------------------------
__global__ void transpose_split(const float* __restrict__ src,
                                bf16* __restrict__ dh, bf16* __restrict__ dl,
                                int Krows, int Ncols) {
    __shared__ float tile[32][33];
    const int nb = blockIdx.x * 32, kb = blockIdx.y * 32;
    const int tx = threadIdx.x, ty = threadIdx.y;   // (32, 8)
#pragma unroll
    for (int j = 0; j < 4; j++) {
        int k = kb + ty + j * 8;
        int n = nb + tx;
        tile[ty + j * 8][tx] = (n < Ncols) ? src[(size_t)k * Ncols + n] : 0.f;
    }
    __syncthreads();
#pragma unroll
    for (int j = 0; j < 4; j++) {
        int n = nb + ty + j * 8;
        int k = kb + tx;
        if (n < Ncols) {
            bf16 h, l;
            splitbf(tile[tx][ty + j * 8], h, l);
            dh[(size_t)n * Krows + k] = h;
            dl[(size_t)n * Krows + k] = l;
        }
    }
}

// ---------------------------- other pack kernels ----------------------------
__global__ void pack_bias(const float* __restrict__ bd,
                          const float* __restrict__ bf,
                          const float* __restrict__ bhh,
                          const float* __restrict__ bih,
                          const float* __restrict__ bh0,
                          const float* __restrict__ bc0) {
    int c = blockIdx.x * 256 + threadIdx.x;
    if (c < HALLN) {
        float v;
        if (c < ATT)            v = bd[c];
        else if (c < ATT + ENC) v = bf[c - ATT];
        else                    v = bhh[c - ATT - ENC] + bih[c - ATT - ENC];
        g_ball[c] = v;
    } else if (c < HALLN + 2 * DEC) {
        int q = c - HALLN;
        g_binit[q] = (q < DEC) ? bh0[q] : bc0[q - DEC];
    }
}

// Fused: split enc_out into bf16 hi/lo + fp16 planes AND compute the
// per-(b,channel) mean over P in the same pass (one 205MB read total).
__global__ void split_mean_kernel(const float* __restrict__ enc_out) {
    const int b  = blockIdx.x;
    const int ch = blockIdx.y * 256 + threadIdx.x;
    const float* src = enc_out + (size_t)b * P * ENC + ch;
    bf16*  Eh = g_E_h + (size_t)b * P * ENC + ch;
    bf16*  El = g_E_l + (size_t)b * P * ENC + ch;
    __half* E16 = g_E16 + (size_t)b * P * ENC + ch;
    float acc = 0.f;
#pragma unroll 4
    for (int p = 0; p < P; p++) {
        float v = src[(size_t)p * ENC];
        acc += v;
        bf16 h, l;
        splitbf(v, h, l);
        Eh[(size_t)p * ENC] = h;
        El[(size_t)p * ENC] = l;
        E16[(size_t)p * ENC] = __float2half_rn(v);
    }
    splitbf(acc * (1.f / 196.f), g_mean_h[b * ENC + ch],
            g_mean_l[b * ENC + ch]);
}

__global__ void split_hc() {
    int idx = blockIdx.x * 256 + threadIdx.x;
    int b = idx / DEC, d = idx % DEC;
    splitbf(g_hc[b * 2 * DEC + d], g_h_h[idx], g_h_l[idx]);
    g_c[idx] = g_hc[b * 2 * DEC + DEC + d];
}

// -------------------------- per-step kernels --------------------------------
// Fused embed + scores + softmax: one block per batch row; encproj in fp16.
__global__ void __launch_bounds__(256)
scores_softmax_kernel(const float* __restrict__ emb,
                      const int* __restrict__ cap,
                      const float* __restrict__ w_att,
                      const float* __restrict__ b_att, int t) {
    __shared__ float s_dec[ATT];
    __shared__ float s_w[ATT];
    __shared__ float s_sc[P];
    __shared__ float red[256];
    int b = blockIdx.x, tid = threadIdx.x;
    int warp = tid >> 5, lane = tid & 31;

    if (tid < 128) {       // embed copy -> x[b, 0:EMB] planes
        int cidx = cap[b * T + t];
        float4 v = reinterpret_cast<const float4*>(
            emb + (size_t)cidx * EMB)[tid];
        int o = b * XDIM + tid * 4;
        splitbf(v.x, g_x_h[o + 0], g_x_l[o + 0]);
        splitbf(v.y, g_x_h[o + 1], g_x_l[o + 1]);
        splitbf(v.z, g_x_h[o + 2], g_x_l[o + 2]);
        splitbf(v.w, g_x_h[o + 3], g_x_l[o + 3]);
    }
    for (int i = tid; i < ATT; i += 256) {
        s_dec[i] = g_hall[b * HALLN + i];
        s_w[i]   = w_att[i];
    }
    __syncthreads();
    float batt = b_att[0];
    for (int p = warp; p < P; p += 8) {
        const __half2* ep2 = reinterpret_cast<const __half2*>(
            g_encproj + ((size_t)(b * P + p)) * ATT);
        float s = 0.f;
#pragma unroll 4
        for (int a2 = lane; a2 < ATT / 2; a2 += 32) {
            __half2 hv = ep2[a2];
            int a = a2 * 2;
            float e0 = __half2float(hv.x) + s_dec[a];
            float e1 = __half2float(hv.y) + s_dec[a + 1];
            s += fmaxf(e0, 0.f) * s_w[a] + fmaxf(e1, 0.f) * s_w[a + 1];
        }
#pragma unroll
        for (int o = 16; o; o >>= 1) s += __shfl_down_sync(0xffffffffu, s, o);
        if (lane == 0) s_sc[p] = s + batt;
    }
    __syncthreads();
    float v = (tid < P) ? s_sc[tid] : -1e30f;
    red[tid] = v;
    __syncthreads();
    for (int o = 128; o; o >>= 1) {
        if (tid < o) red[tid] = fmaxf(red[tid], red[tid + o]);
        __syncthreads();
    }
    float m = red[0];
    __syncthreads();
    float e = (tid < P) ? expf(v - m) : 0.f;
    red[tid] = e;
    __syncthreads();
    for (int o = 128; o; o >>= 1) {
        if (tid < o) red[tid] += red[tid + o];
        __syncthreads();
    }
    if (tid < P) g_alpha[b * P + tid] = e / red[0];
}

// x[b, EMB+ch] = sigmoid(fbeta) * sum_p alpha[b,p]*E16[b,p,ch]
__global__ void context_kernel() {
    __shared__ float s_a[P];
    int b = blockIdx.x, tid = threadIdx.x;
    int ch = blockIdx.y * 512 + tid * 2;
    if (tid < P) s_a[tid] = g_alpha[b * P + tid];
    __syncthreads();
    const __half* base = g_E16 + (size_t)b * P * ENC + ch;
    float ax = 0.f, ay = 0.f;
#pragma unroll 4
    for (int p = 0; p < P; p++) {
        __half2 v = *reinterpret_cast<const __half2*>(base + (size_t)p * ENC);
        float a = s_a[p];
        ax = fmaf(a, __half2float(v.x), ax);
        ay = fmaf(a, __half2float(v.y), ay);
    }
    float g0 = 1.f / (1.f + expf(-g_hall[b * HALLN + ATT + ch]));
    float g1 = 1.f / (1.f + expf(-g_hall[b * HALLN + ATT + ch + 1]));
    int o = b * XDIM + EMB + ch;
    splitbf(g0 * ax, g_x_h[o], g_x_l[o]);
    splitbf(g1 * ay, g_x_h[o + 1], g_x_l[o + 1]);
}

// Deterministic split-K reduce + LSTM cell; writes h planes + c.
__global__ void lstm_kernel() {
    int idx = blockIdx.x * 256 + threadIdx.x;
    int b = idx / DEC, d = idx % DEC;
    const float* hallg = &g_hall[b * HALLN + ATT + ENC];
    float gi = hallg[d];
    float gf = hallg[DEC + d];
    float gg = hallg[2 * DEC + d];
    float go = hallg[3 * DEC + d];
#pragma unroll
    for (int s = 0; s < KSPLIT; s++) {
        const float* pp = &g_gpart[((size_t)s * B + b) * G4];
        gi += pp[d];
        gf += pp[DEC + d];
        gg += pp[2 * DEC + d];
        go += pp[3 * DEC + d];
    }
    float c  = g_c[idx];
    float si = 1.f / (1.f + expf(-gi));
    float sf = 1.f / (1.f + expf(-gf));
    float so = 1.f / (1.f + expf(-go));
    float cn = sf * c + si * tanhf(gg);
    float hn = so * tanhf(cn);
    g_c[idx] = cn;
    splitbf(hn, g_h_h[idx], g_h_l[idx]);
}

// ------------------------------- launcher -----------------------------------
extern "C" void kernel_launch(void* const* d_in, const int* in_sizes, int n_in,
                              void* d_out, int out_size) {
    const float* enc_out   = (const float*)d_in[0];
    const int*   captions  = (const int*)  d_in[1];
    const float* emb       = (const float*)d_in[2];
    const float* W_init_h  = (const float*)d_in[3];
    const float* b_init_h  = (const float*)d_in[4];
    const float* W_init_c  = (const float*)d_in[5];
    const float* b_init_c  = (const float*)d_in[6];
    const float* W_enc_att = (const float*)d_in[7];
    const float* b_enc_att = (const float*)d_in[8];
    const float* W_dec_att = (const float*)d_in[9];
    const float* b_dec_att = (const float*)d_in[10];
    const float* w_att     = (const float*)d_in[11];
    const float* b_att     = (const float*)d_in[12];
    const float* W_fbeta   = (const float*)d_in[13];
    const float* b_fbeta   = (const float*)d_in[14];
    const float* W_ih      = (const float*)d_in[15];
    const float* b_ih      = (const float*)d_in[16];
    const float* W_hh      = (const float*)d_in[17];
    const float* b_hh      = (const float*)d_in[18];
    const float* W_fc      = (const float*)d_in[19];
    const float* b_fc      = (const float*)d_in[20];
    float* out = (float*)d_out;

    bf16 *pMh, *pMl, *pHh, *pHl, *pXh, *pXl, *pEh, *pEl;
    bf16 *pWencH, *pWencL, *pWinH, *pWinL, *pWcH, *pWcL, *pWihH, *pWihL;
    float *p_hc, *p_hall, *p_gpart, *p_ball, *p_binit;
    __half* p_encproj;
    cudaGetSymbolAddress((void**)&pEh, g_E_h);
    cudaGetSymbolAddress((void**)&pEl, g_E_l);
    cudaGetSymbolAddress((void**)&pMh, g_mean_h);
    cudaGetSymbolAddress((void**)&pMl, g_mean_l);
    cudaGetSymbolAddress((void**)&pHh, g_h_h);
    cudaGetSymbolAddress((void**)&pHl, g_h_l);
    cudaGetSymbolAddress((void**)&pXh, g_x_h);
    cudaGetSymbolAddress((void**)&pXl, g_x_l);
    cudaGetSymbolAddress((void**)&pWencH, g_WencT_h);
    cudaGetSymbolAddress((void**)&pWencL, g_WencT_l);
    cudaGetSymbolAddress((void**)&pWinH, g_WinitT_h);
    cudaGetSymbolAddress((void**)&pWinL, g_WinitT_l);
    cudaGetSymbolAddress((void**)&pWcH, g_WcombT_h);
    cudaGetSymbolAddress((void**)&pWcL, g_WcombT_l);
    cudaGetSymbolAddress((void**)&pWihH, g_WihT_h);
    cudaGetSymbolAddress((void**)&pWihL, g_WihT_l);
    cudaGetSymbolAddress((void**)&p_hc, g_hc);
    cudaGetSymbolAddress((void**)&p_encproj, g_encproj);
    cudaGetSymbolAddress((void**)&p_hall, g_hall);
    cudaGetSymbolAddress((void**)&p_gpart, g_gpart);
    cudaGetSymbolAddress((void**)&p_ball, g_ball);
    cudaGetSymbolAddress((void**)&p_binit, g_binit);

    cudaFuncSetAttribute(gemm_bf3<8, false, 2, 3>,
                         cudaFuncAttributeMaxDynamicSharedMemorySize,
                         SMEM_N8_2_P3);
    cudaFuncSetAttribute(gemm_bf3<8, true, 2, 2>,
                         cudaFuncAttributeMaxDynamicSharedMemorySize,
                         SMEM_N8_2_P2);
    cudaFuncSetAttribute(gemm_bf3<4, false, 3, 3>,
                         cudaFuncAttributeMaxDynamicSharedMemorySize,
                         SMEM_N4_3_P3);

    // ---- one-time precompute: coalesced transposes ----
    dim3 tb(32, 8);
    transpose_split<<<dim3(ATT / 32, ENC / 32), tb>>>(
        W_enc_att, pWencH, pWencL, ENC, ATT);
    transpose_split<<<dim3(DEC / 32, ENC / 32), tb>>>(
        W_init_h, pWinH, pWinL, ENC, DEC);
    transpose_split<<<dim3(DEC / 32, ENC / 32), tb>>>(
        W_init_c, pWinH + (size_t)DEC * ENC, pWinL + (size_t)DEC * ENC, ENC,
        DEC);
    transpose_split<<<dim3(ATT / 32, DEC / 32), tb>>>(
        W_dec_att, pWcH, pWcL, DEC, ATT);
    transpose_split<<<dim3(ENC / 32, DEC / 32), tb>>>(
        W_fbeta, pWcH + (size_t)ATT * DEC, pWcL + (size_t)ATT * DEC, DEC, ENC);
    transpose_split<<<dim3(G4 / 32, DEC / 32), tb>>>(
        W_hh, pWcH + (size_t)(ATT + ENC) * DEC, pWcL + (size_t)(ATT + ENC) * DEC,
        DEC, G4);
    transpose_split<<<dim3((VOC + 31) / 32, DEC / 32), tb>>>(
        W_fc, pWcH + (size_t)HALLN * DEC, pWcL + (size_t)HALLN * DEC, DEC, VOC);
    transpose_split<<<dim3(G4 / 32, XDIM / 32), tb>>>(
        W_ih, pWihH, pWihL, XDIM, G4);

    pack_bias<<<(HALLN + 2 * DEC + 255) / 256, 256>>>(b_dec_att, b_fbeta, b_hh,
                                                      b_ih, b_init_h, b_init_c);
    // fused split + mean (single pass over enc_out)
    split_mean_kernel<<<dim3(B, ENC / 256), 256>>>(enc_out);

    // enc_proj = enc_out @ W_enc_att + b  -> fp16, 2-pass (scores path only)
    gemm_bf3<8, true, 2, 2><<<dim3(ATT / 128, B * P / 128, 1), 256,
                              SMEM_N8_2_P2>>>(
        pEh, pEl, pWencH, pWencL, p_encproj, nullptr, B * P, ATT, ATT, ENC,
        ATT, 0, b_enc_att, nullptr, ENC);

    // [h0|c0] = mean @ [W_init_h|W_init_c] + b  (3-pass: recurrent init)
    gemm_bf3<8, false, 2, 3><<<dim3(2 * DEC / 128, 1, 1), 256,
                               SMEM_N8_2_P3>>>(
        pMh, pMl, pWinH, pWinL, p_hc, nullptr, B, 2 * DEC, 2 * DEC, ENC,
        2 * DEC, 0, p_binit, nullptr, ENC);
    split_hc<<<B * DEC / 256, 256>>>();

    // hall(0) = h0 @ Wall + ball  (3-pass)
    gemm_bf3<8, false, 2, 3><<<dim3(HALLN / 128, 1, 1), 256, SMEM_N8_2_P3>>>(
        pHh, pHl, pWcH, pWcL, p_hall, nullptr, B, HALLN, HALLN, DEC, HALLN, 0,
        p_ball, nullptr, DEC);

    // ---- decode loop ----
    for (int t = 0; t < NSTEP; t++) {
        scores_softmax_kernel<<<B, 256>>>(emb, captions, w_att, b_att, t);
        context_kernel<<<dim3(B, ENC / 512), 256>>>();

        // gates partials = x @ W_ih, split-K (8 x 32 = 256 CTAs), 3-pass
        gemm_bf3<4, false, 3, 3><<<dim3(G4 / 64, 1, KSPLIT), 256,
                                   SMEM_N4_3_P3>>>(
            pXh, pXl, pWihH, pWihL, p_gpart, nullptr, B, G4, G4, XDIM, G4, 0,
            nullptr, nullptr, KCHUNK);

        lstm_kernel<<<B * DEC / 256, 256>>>();

        // combined: [hall(t+1) | fc(t)] = h @ [Wall | Wfc], 3-pass
        gemm_bf3<4, false, 3, 3><<<dim3((COMBN + 63) / 64, 1, 1), 256,
                                   SMEM_N4_3_P3>>>(
            pHh, pHl, pWcH, pWcL, p_hall, out + (size_t)t * VOC, B, COMBN,
            HALLN, DEC, HALLN, NSTEP * VOC, p_ball, b_fc, DEC);
    }
}